// round 14
// baseline (speedup 1.0000x reference)
#include <cuda_runtime.h>
#include <cstdint>

// ---------------------------------------------------------------------------
// Problem constants
// ---------------------------------------------------------------------------
#define BT    32768      // 16 * 2048 rows
#define FSZ   768        // K
#define GN    640        // N = groups * num_vars
#define NV    320
#define VD    128
#define QCOLS 256
#define EPS_F 1e-7

// GEMM tiling
#define BM 128
#define BN 128
#define BK 16
#define NKT (FSZ / BK)   // 48

#define PP_BLOCKS 512

// Scratch (device globals: allocation-free rule)
__device__ float g_logits[(size_t)BT * GN];          // 84 MB
__device__ float g_partials[PP_BLOCKS * GN];         // 1.3 MB
__device__ double g_colsum[GN];

// ---------------------------------------------------------------------------
// Packed fp32x2 helpers (sm_103 FFMA2 — only reachable via PTX)
// ---------------------------------------------------------------------------
__device__ __forceinline__ unsigned long long pack2(float lo, float hi) {
    unsigned long long r;
    asm("mov.b64 %0, {%1, %2};" : "=l"(r)
        : "r"(__float_as_uint(lo)), "r"(__float_as_uint(hi)));
    return r;
}
__device__ __forceinline__ void unpack2(unsigned long long v, float& lo, float& hi) {
    unsigned int a, b;
    asm("mov.b64 {%0, %1}, %2;" : "=r"(a), "=r"(b) : "l"(v));
    lo = __uint_as_float(a);
    hi = __uint_as_float(b);
}
__device__ __forceinline__ unsigned long long ffma2(unsigned long long a,
                                                    unsigned long long b,
                                                    unsigned long long c) {
    unsigned long long d;
    asm("fma.rn.f32x2 %0, %1, %2, %3;" : "=l"(d) : "l"(a), "l"(b), "l"(c));
    return d;
}

// ---------------------------------------------------------------------------
// Kernel 1: fp32 GEMM  g_logits = x @ W + b
//   128x128 tile, BK=16, 256 threads, 8x8/thread via FFMA2,
//   DOUBLE-BUFFERED smem: one __syncthreads per K-step.
// ---------------------------------------------------------------------------
__global__ __launch_bounds__(256, 2)
void gvq_gemm_kernel(const float* __restrict__ x,
                     const float* __restrict__ W,
                     const float* __restrict__ bias) {
    __shared__ float As[2][BK][BM + 4];
    __shared__ float Bs[2][BK][BN];

    const int tid = threadIdx.x;
    const int m0  = blockIdx.y * BM;
    const int n0  = blockIdx.x * BN;
    const int tx  = tid & 15;          // n direction
    const int ty  = tid >> 4;          // m direction

    // A-tile: 512 float4 / 256 threads = 2 each
    const int a_row0 = tid >> 2;                 // 0..63
    const int a_row1 = (tid + 256) >> 2;         // 64..127
    const int a_k    = (tid & 3) * 4;            // 0,4,8,12
    // B-tile
    const int b_k0 = tid >> 5;                   // 0..7
    const int b_k1 = (tid + 256) >> 5;           // 8..15
    const int b_n  = (tid & 31) * 4;             // 0..124

    unsigned long long acc[8][4];
#pragma unroll
    for (int i = 0; i < 8; i++)
#pragma unroll
        for (int p = 0; p < 4; p++) acc[i][p] = 0ULL;

    const float* xa = x + (size_t)m0 * FSZ;

    // prefetch tile 0 into registers
    float4 va0 = *(const float4*)(xa + (size_t)a_row0 * FSZ + a_k);
    float4 va1 = *(const float4*)(xa + (size_t)a_row1 * FSZ + a_k);
    float4 vb0 = *(const float4*)(W + (size_t)b_k0 * GN + n0 + b_n);
    float4 vb1 = *(const float4*)(W + (size_t)b_k1 * GN + n0 + b_n);

    // store tile 0 into buffer 0
    As[0][a_k + 0][a_row0] = va0.x;
    As[0][a_k + 1][a_row0] = va0.y;
    As[0][a_k + 2][a_row0] = va0.z;
    As[0][a_k + 3][a_row0] = va0.w;
    As[0][a_k + 0][a_row1] = va1.x;
    As[0][a_k + 1][a_row1] = va1.y;
    As[0][a_k + 2][a_row1] = va1.z;
    As[0][a_k + 3][a_row1] = va1.w;
    *(float4*)&Bs[0][b_k0][b_n] = vb0;
    *(float4*)&Bs[0][b_k1][b_n] = vb1;
    __syncthreads();

    for (int kt = 0; kt < NKT; kt++) {
        const int buf = kt & 1;

        // issue next tile's global loads early (overlap with compute)
        if (kt + 1 < NKT) {
            const int kb = (kt + 1) * BK;
            va0 = *(const float4*)(xa + (size_t)a_row0 * FSZ + kb + a_k);
            va1 = *(const float4*)(xa + (size_t)a_row1 * FSZ + kb + a_k);
            vb0 = *(const float4*)(W + (size_t)(kb + b_k0) * GN + n0 + b_n);
            vb1 = *(const float4*)(W + (size_t)(kb + b_k1) * GN + n0 + b_n);
        }

#pragma unroll
        for (int k = 0; k < BK; k++) {
            const float4 a0 = *(const float4*)&As[buf][k][ty * 4];
            const float4 a1 = *(const float4*)&As[buf][k][64 + ty * 4];
            const float4 b0 = *(const float4*)&Bs[buf][k][tx * 4];
            const float4 b1 = *(const float4*)&Bs[buf][k][64 + tx * 4];

            unsigned long long bp[4];
            bp[0] = pack2(b0.x, b0.y);
            bp[1] = pack2(b0.z, b0.w);
            bp[2] = pack2(b1.x, b1.y);
            bp[3] = pack2(b1.z, b1.w);

            const float av[8] = {a0.x, a0.y, a0.z, a0.w, a1.x, a1.y, a1.z, a1.w};
#pragma unroll
            for (int i = 0; i < 8; i++) {
                const unsigned long long aa = pack2(av[i], av[i]);
#pragma unroll
                for (int p = 0; p < 4; p++)
                    acc[i][p] = ffma2(aa, bp[p], acc[i][p]);
            }
        }

        // store next tile into the other buffer; single barrier per step
        if (kt + 1 < NKT) {
            const int nb = buf ^ 1;
            As[nb][a_k + 0][a_row0] = va0.x;
            As[nb][a_k + 1][a_row0] = va0.y;
            As[nb][a_k + 2][a_row0] = va0.z;
            As[nb][a_k + 3][a_row0] = va0.w;
            As[nb][a_k + 0][a_row1] = va1.x;
            As[nb][a_k + 1][a_row1] = va1.y;
            As[nb][a_k + 2][a_row1] = va1.z;
            As[nb][a_k + 3][a_row1] = va1.w;
            *(float4*)&Bs[nb][b_k0][b_n] = vb0;
            *(float4*)&Bs[nb][b_k1][b_n] = vb1;
            __syncthreads();
        }
    }

    // epilogue: add bias, store fp32 logits
    const float4 bb0 = *(const float4*)(bias + n0 + tx * 4);
    const float4 bb1 = *(const float4*)(bias + n0 + 64 + tx * 4);

#pragma unroll
    for (int i = 0; i < 8; i++) {
        const int m = (i < 4) ? (m0 + ty * 4 + i) : (m0 + 64 + ty * 4 + (i - 4));
        float c0, c1, c2, c3;
        unpack2(acc[i][0], c0, c1);
        unpack2(acc[i][1], c2, c3);
        float4 o0 = make_float4(c0 + bb0.x, c1 + bb0.y, c2 + bb0.z, c3 + bb0.w);
        *(float4*)(g_logits + (size_t)m * GN + n0 + tx * 4) = o0;

        unpack2(acc[i][2], c0, c1);
        unpack2(acc[i][3], c2, c3);
        float4 o1 = make_float4(c0 + bb1.x, c1 + bb1.y, c2 + bb1.z, c3 + bb1.w);
        *(float4*)(g_logits + (size_t)m * GN + n0 + 64 + tx * 4) = o1;
    }
}

// ---------------------------------------------------------------------------
// Kernel 2: per-row argmax + codebook gather + softmax prob accumulation
// ---------------------------------------------------------------------------
__global__ __launch_bounds__(256)
void gvq_postproc_kernel(const float* __restrict__ codebook,
                         float* __restrict__ qout) {
    __shared__ float sacc[GN];
    const int tid  = threadIdx.x;
    const int w    = tid >> 5;
    const int lane = tid & 31;

    for (int i = tid; i < GN; i += 256) sacc[i] = 0.0f;
    __syncthreads();

    float pacc[2][10];
#pragma unroll
    for (int g = 0; g < 2; g++)
#pragma unroll
        for (int j = 0; j < 10; j++) pacc[g][j] = 0.0f;

    const int row0 = blockIdx.x * 64 + w * 8;

    for (int rr = 0; rr < 8; rr++) {
        const int row = row0 + rr;
        const float* lg = g_logits + (size_t)row * GN;

#pragma unroll
        for (int g = 0; g < 2; g++) {
            const float* base = lg + g * NV;
            float v[10];
#pragma unroll
            for (int j = 0; j < 10; j++) v[j] = base[lane + 32 * j];

            // argmax (first-occurrence tie rule, matching jnp.argmax)
            float m = v[0];
            int   mi = lane;
#pragma unroll
            for (int j = 1; j < 10; j++)
                if (v[j] > m) { m = v[j]; mi = lane + 32 * j; }
#pragma unroll
            for (int off = 16; off > 0; off >>= 1) {
                const float om  = __shfl_xor_sync(0xffffffffu, m, off);
                const int   omi = __shfl_xor_sync(0xffffffffu, mi, off);
                if (om > m || (om == m && omi < mi)) { m = om; mi = omi; }
            }

            // softmax
            float e[10];
            float s = 0.0f;
#pragma unroll
            for (int j = 0; j < 10; j++) { e[j] = __expf(v[j] - m); s += e[j]; }
#pragma unroll
            for (int off = 16; off > 0; off >>= 1)
                s += __shfl_xor_sync(0xffffffffu, s, off);
            const float inv = 1.0f / s;
#pragma unroll
            for (int j = 0; j < 10; j++) pacc[g][j] += e[j] * inv;

            // hard one-hot x codebook == gather of codebook row mi
            const float4* src = (const float4*)(codebook + ((size_t)(g * NV + mi)) * VD);
            float4* dst = (float4*)(qout + (size_t)row * QCOLS + g * VD);
            dst[lane] = src[lane];
        }
    }

#pragma unroll
    for (int g = 0; g < 2; g++)
#pragma unroll
        for (int j = 0; j < 10; j++)
            atomicAdd(&sacc[g * NV + lane + 32 * j], pacc[g][j]);
    __syncthreads();

    for (int i = tid; i < GN; i += 256)
        g_partials[(size_t)blockIdx.x * GN + i] = sacc[i];
}

// ---------------------------------------------------------------------------
// Kernel 3a: parallel per-column reduction (640 blocks x 128 threads)
// ---------------------------------------------------------------------------
__global__ __launch_bounds__(128)
void gvq_reduce_kernel() {
    __shared__ double sd[128];
    const int v = blockIdx.x, t = threadIdx.x;
    double s = 0.0;
    for (int b = t; b < PP_BLOCKS; b += 128)
        s += (double)g_partials[(size_t)b * GN + v];
    sd[t] = s;
    __syncthreads();
    for (int o = 64; o > 0; o >>= 1) {
        if (t < o) sd[t] += sd[t + o];
        __syncthreads();
    }
    if (t == 0) g_colsum[v] = sd[0];
}

// ---------------------------------------------------------------------------
// Kernel 3b: perplexity scalars
// ---------------------------------------------------------------------------
__global__ void gvq_finalize_kernel(float* __restrict__ out_scalars) {
    __shared__ double sterm[GN];
    const int v = threadIdx.x;  // 640 threads
    const double avg = g_colsum[v] * (1.0 / (double)BT);
    sterm[v] = avg * log(avg + EPS_F);   // reference's +1e-7 inside the log
    __syncthreads();
    if (v == 0) {
        double h0 = 0.0, h1 = 0.0;
        for (int i = 0; i < NV; i++) h0 += sterm[i];
        for (int i = 0; i < NV; i++) h1 += sterm[NV + i];
        const double ppl = exp(-h0) + exp(-h1);
        out_scalars[0] = (float)(((double)GN - ppl) / (double)GN);
        out_scalars[1] = 2.0f;  // CURR_TEMP
    }
}

// ---------------------------------------------------------------------------
// Launch
// ---------------------------------------------------------------------------
extern "C" void kernel_launch(void* const* d_in, const int* in_sizes, int n_in,
                              void* d_out, int out_size) {
    const float* x    = (const float*)d_in[0];   // [16,2048,768]
    const float* W    = (const float*)d_in[1];   // [768,640]
    const float* bias = (const float*)d_in[2];   // [640]
    const float* cb   = (const float*)d_in[3];   // [1,640,128]
    float* out = (float*)d_out;

    dim3 ggrid(GN / BN, BT / BM);  // (5, 256)
    gvq_gemm_kernel<<<ggrid, 256>>>(x, W, bias);
    gvq_postproc_kernel<<<PP_BLOCKS, 256>>>(cb, out);
    gvq_reduce_kernel<<<GN, 128>>>();
    gvq_finalize_kernel<<<1, GN>>>(out + (size_t)BT * QCOLS);

    (void)in_sizes; (void)n_in; (void)out_size;
}

// round 15
// speedup vs baseline: 1.0025x; 1.0025x over previous
#include <cuda_runtime.h>
#include <cstdint>

// ---------------------------------------------------------------------------
// Problem constants
// ---------------------------------------------------------------------------
#define BT    32768      // 16 * 2048 rows
#define FSZ   768        // K
#define GN    640        // N = groups * num_vars
#define NV    320
#define VD    128
#define QCOLS 256
#define EPS_F 1e-7

// GEMM tiling
#define BM 128
#define BN 128
#define BK 16
#define NKT (FSZ / BK)   // 48

#define PP_BLOCKS 512

// Scratch (device globals: allocation-free rule)
__device__ float g_logits[(size_t)BT * GN];          // 84 MB
__device__ float g_partials[PP_BLOCKS * GN];         // 1.3 MB
__device__ double g_colsum[GN];

// ---------------------------------------------------------------------------
// Packed fp32x2 helpers (sm_103 FFMA2 — only reachable via PTX)
// ---------------------------------------------------------------------------
__device__ __forceinline__ unsigned long long pack2(float lo, float hi) {
    unsigned long long r;
    asm("mov.b64 %0, {%1, %2};" : "=l"(r)
        : "r"(__float_as_uint(lo)), "r"(__float_as_uint(hi)));
    return r;
}
__device__ __forceinline__ void unpack2(unsigned long long v, float& lo, float& hi) {
    unsigned int a, b;
    asm("mov.b64 {%0, %1}, %2;" : "=r"(a), "=r"(b) : "l"(v));
    lo = __uint_as_float(a);
    hi = __uint_as_float(b);
}
__device__ __forceinline__ unsigned long long ffma2(unsigned long long a,
                                                    unsigned long long b,
                                                    unsigned long long c) {
    unsigned long long d;
    asm("fma.rn.f32x2 %0, %1, %2, %3;" : "=l"(d) : "l"(a), "l"(b), "l"(c));
    return d;
}

// ---------------------------------------------------------------------------
// Kernel 1: fp32 GEMM  g_logits = x @ W + b
//   128x128 tile, BK=16, 256 threads, 8x8/thread via FFMA2,
//   DOUBLE-BUFFERED smem: one __syncthreads per K-step.
// ---------------------------------------------------------------------------
__global__ __launch_bounds__(256, 2)
void gvq_gemm_kernel(const float* __restrict__ x,
                     const float* __restrict__ W,
                     const float* __restrict__ bias) {
    __shared__ float As[2][BK][BM + 4];
    __shared__ float Bs[2][BK][BN];

    const int tid = threadIdx.x;
    const int m0  = blockIdx.y * BM;
    const int n0  = blockIdx.x * BN;
    const int tx  = tid & 15;          // n direction
    const int ty  = tid >> 4;          // m direction

    // A-tile: 512 float4 / 256 threads = 2 each
    const int a_row0 = tid >> 2;                 // 0..63
    const int a_row1 = (tid + 256) >> 2;         // 64..127
    const int a_k    = (tid & 3) * 4;            // 0,4,8,12
    // B-tile
    const int b_k0 = tid >> 5;                   // 0..7
    const int b_k1 = (tid + 256) >> 5;           // 8..15
    const int b_n  = (tid & 31) * 4;             // 0..124

    unsigned long long acc[8][4];
#pragma unroll
    for (int i = 0; i < 8; i++)
#pragma unroll
        for (int p = 0; p < 4; p++) acc[i][p] = 0ULL;

    const float* xa = x + (size_t)m0 * FSZ;

    // prefetch tile 0 into registers
    float4 va0 = *(const float4*)(xa + (size_t)a_row0 * FSZ + a_k);
    float4 va1 = *(const float4*)(xa + (size_t)a_row1 * FSZ + a_k);
    float4 vb0 = *(const float4*)(W + (size_t)b_k0 * GN + n0 + b_n);
    float4 vb1 = *(const float4*)(W + (size_t)b_k1 * GN + n0 + b_n);

    // store tile 0 into buffer 0
    As[0][a_k + 0][a_row0] = va0.x;
    As[0][a_k + 1][a_row0] = va0.y;
    As[0][a_k + 2][a_row0] = va0.z;
    As[0][a_k + 3][a_row0] = va0.w;
    As[0][a_k + 0][a_row1] = va1.x;
    As[0][a_k + 1][a_row1] = va1.y;
    As[0][a_k + 2][a_row1] = va1.z;
    As[0][a_k + 3][a_row1] = va1.w;
    *(float4*)&Bs[0][b_k0][b_n] = vb0;
    *(float4*)&Bs[0][b_k1][b_n] = vb1;
    __syncthreads();

    for (int kt = 0; kt < NKT; kt++) {
        const int buf = kt & 1;

        // issue next tile's global loads early (overlap with compute)
        if (kt + 1 < NKT) {
            const int kb = (kt + 1) * BK;
            va0 = *(const float4*)(xa + (size_t)a_row0 * FSZ + kb + a_k);
            va1 = *(const float4*)(xa + (size_t)a_row1 * FSZ + kb + a_k);
            vb0 = *(const float4*)(W + (size_t)(kb + b_k0) * GN + n0 + b_n);
            vb1 = *(const float4*)(W + (size_t)(kb + b_k1) * GN + n0 + b_n);
        }

#pragma unroll
        for (int k = 0; k < BK; k++) {
            const float4 a0 = *(const float4*)&As[buf][k][ty * 4];
            const float4 a1 = *(const float4*)&As[buf][k][64 + ty * 4];
            const float4 b0 = *(const float4*)&Bs[buf][k][tx * 4];
            const float4 b1 = *(const float4*)&Bs[buf][k][64 + tx * 4];

            unsigned long long bp[4];
            bp[0] = pack2(b0.x, b0.y);
            bp[1] = pack2(b0.z, b0.w);
            bp[2] = pack2(b1.x, b1.y);
            bp[3] = pack2(b1.z, b1.w);

            const float av[8] = {a0.x, a0.y, a0.z, a0.w, a1.x, a1.y, a1.z, a1.w};
#pragma unroll
            for (int i = 0; i < 8; i++) {
                const unsigned long long aa = pack2(av[i], av[i]);
#pragma unroll
                for (int p = 0; p < 4; p++)
                    acc[i][p] = ffma2(aa, bp[p], acc[i][p]);
            }
        }

        // store next tile into the other buffer; single barrier per step
        if (kt + 1 < NKT) {
            const int nb = buf ^ 1;
            As[nb][a_k + 0][a_row0] = va0.x;
            As[nb][a_k + 1][a_row0] = va0.y;
            As[nb][a_k + 2][a_row0] = va0.z;
            As[nb][a_k + 3][a_row0] = va0.w;
            As[nb][a_k + 0][a_row1] = va1.x;
            As[nb][a_k + 1][a_row1] = va1.y;
            As[nb][a_k + 2][a_row1] = va1.z;
            As[nb][a_k + 3][a_row1] = va1.w;
            *(float4*)&Bs[nb][b_k0][b_n] = vb0;
            *(float4*)&Bs[nb][b_k1][b_n] = vb1;
            __syncthreads();
        }
    }

    // epilogue: add bias, store fp32 logits
    const float4 bb0 = *(const float4*)(bias + n0 + tx * 4);
    const float4 bb1 = *(const float4*)(bias + n0 + 64 + tx * 4);

#pragma unroll
    for (int i = 0; i < 8; i++) {
        const int m = (i < 4) ? (m0 + ty * 4 + i) : (m0 + 64 + ty * 4 + (i - 4));
        float c0, c1, c2, c3;
        unpack2(acc[i][0], c0, c1);
        unpack2(acc[i][1], c2, c3);
        float4 o0 = make_float4(c0 + bb0.x, c1 + bb0.y, c2 + bb0.z, c3 + bb0.w);
        *(float4*)(g_logits + (size_t)m * GN + n0 + tx * 4) = o0;

        unpack2(acc[i][2], c0, c1);
        unpack2(acc[i][3], c2, c3);
        float4 o1 = make_float4(c0 + bb1.x, c1 + bb1.y, c2 + bb1.z, c3 + bb1.w);
        *(float4*)(g_logits + (size_t)m * GN + n0 + 64 + tx * 4) = o1;
    }
}

// ---------------------------------------------------------------------------
// Kernel 2: per-row argmax + codebook gather + softmax prob accumulation
// ---------------------------------------------------------------------------
__global__ __launch_bounds__(256)
void gvq_postproc_kernel(const float* __restrict__ codebook,
                         float* __restrict__ qout) {
    __shared__ float sacc[GN];
    const int tid  = threadIdx.x;
    const int w    = tid >> 5;
    const int lane = tid & 31;

    for (int i = tid; i < GN; i += 256) sacc[i] = 0.0f;
    __syncthreads();

    float pacc[2][10];
#pragma unroll
    for (int g = 0; g < 2; g++)
#pragma unroll
        for (int j = 0; j < 10; j++) pacc[g][j] = 0.0f;

    const int row0 = blockIdx.x * 64 + w * 8;

    for (int rr = 0; rr < 8; rr++) {
        const int row = row0 + rr;
        const float* lg = g_logits + (size_t)row * GN;

#pragma unroll
        for (int g = 0; g < 2; g++) {
            const float* base = lg + g * NV;
            float v[10];
#pragma unroll
            for (int j = 0; j < 10; j++) v[j] = base[lane + 32 * j];

            // argmax (first-occurrence tie rule, matching jnp.argmax)
            float m = v[0];
            int   mi = lane;
#pragma unroll
            for (int j = 1; j < 10; j++)
                if (v[j] > m) { m = v[j]; mi = lane + 32 * j; }
#pragma unroll
            for (int off = 16; off > 0; off >>= 1) {
                const float om  = __shfl_xor_sync(0xffffffffu, m, off);
                const int   omi = __shfl_xor_sync(0xffffffffu, mi, off);
                if (om > m || (om == m && omi < mi)) { m = om; mi = omi; }
            }

            // softmax
            float e[10];
            float s = 0.0f;
#pragma unroll
            for (int j = 0; j < 10; j++) { e[j] = __expf(v[j] - m); s += e[j]; }
#pragma unroll
            for (int off = 16; off > 0; off >>= 1)
                s += __shfl_xor_sync(0xffffffffu, s, off);
            const float inv = 1.0f / s;
#pragma unroll
            for (int j = 0; j < 10; j++) pacc[g][j] += e[j] * inv;

            // hard one-hot x codebook == gather of codebook row mi
            const float4* src = (const float4*)(codebook + ((size_t)(g * NV + mi)) * VD);
            float4* dst = (float4*)(qout + (size_t)row * QCOLS + g * VD);
            dst[lane] = src[lane];
        }
    }

#pragma unroll
    for (int g = 0; g < 2; g++)
#pragma unroll
        for (int j = 0; j < 10; j++)
            atomicAdd(&sacc[g * NV + lane + 32 * j], pacc[g][j]);
    __syncthreads();

    for (int i = tid; i < GN; i += 256)
        g_partials[(size_t)blockIdx.x * GN + i] = sacc[i];
}

// ---------------------------------------------------------------------------
// Kernel 3a: parallel per-column reduction (640 blocks x 128 threads)
// ---------------------------------------------------------------------------
__global__ __launch_bounds__(128)
void gvq_reduce_kernel() {
    __shared__ double sd[128];
    const int v = blockIdx.x, t = threadIdx.x;
    double s = 0.0;
    for (int b = t; b < PP_BLOCKS; b += 128)
        s += (double)g_partials[(size_t)b * GN + v];
    sd[t] = s;
    __syncthreads();
    for (int o = 64; o > 0; o >>= 1) {
        if (t < o) sd[t] += sd[t + o];
        __syncthreads();
    }
    if (t == 0) g_colsum[v] = sd[0];
}

// ---------------------------------------------------------------------------
// Kernel 3b: perplexity scalars
// ---------------------------------------------------------------------------
__global__ void gvq_finalize_kernel(float* __restrict__ out_scalars) {
    __shared__ double sterm[GN];
    const int v = threadIdx.x;  // 640 threads
    const double avg = g_colsum[v] * (1.0 / (double)BT);
    sterm[v] = avg * log(avg + EPS_F);   // reference's +1e-7 inside the log
    __syncthreads();
    if (v == 0) {
        double h0 = 0.0, h1 = 0.0;
        for (int i = 0; i < NV; i++) h0 += sterm[i];
        for (int i = 0; i < NV; i++) h1 += sterm[NV + i];
        const double ppl = exp(-h0) + exp(-h1);
        out_scalars[0] = (float)(((double)GN - ppl) / (double)GN);
        out_scalars[1] = 2.0f;  // CURR_TEMP
    }
}

// ---------------------------------------------------------------------------
// Launch
// ---------------------------------------------------------------------------
extern "C" void kernel_launch(void* const* d_in, const int* in_sizes, int n_in,
                              void* d_out, int out_size) {
    const float* x    = (const float*)d_in[0];   // [16,2048,768]
    const float* W    = (const float*)d_in[1];   // [768,640]
    const float* bias = (const float*)d_in[2];   // [640]
    const float* cb   = (const float*)d_in[3];   // [1,640,128]
    float* out = (float*)d_out;

    dim3 ggrid(GN / BN, BT / BM);  // (5, 256)
    gvq_gemm_kernel<<<ggrid, 256>>>(x, W, bias);
    gvq_postproc_kernel<<<PP_BLOCKS, 256>>>(cb, out);
    gvq_reduce_kernel<<<GN, 128>>>();
    gvq_finalize_kernel<<<1, GN>>>(out + (size_t)BT * QCOLS);

    (void)in_sizes; (void)n_in; (void)out_size;
}